// round 12
// baseline (speedup 1.0000x reference)
#include <cuda_runtime.h>
#include <math.h>

#define CCH 512
#define BB  32
#define HW  4096
#define BN_EPS 1e-5f

#define RED_BLOCKS (BB * CCH)
#define PF_BLOCKS  512          // tail blocks that prefetch conv_w into L2
#define PF_FLOATS  (CCH * CCH / PF_BLOCKS)   // 512 floats = 2KB per block

// Per-(b,c) pooled values (already includes pos-embed term and /4096).
__device__ float g_pooled[BB * CCH];

// 49 bilinear pooling weights A[i]*A[j], computed host-side, passed by value.
struct PEW { float w[49]; };

// ---------------------------------------------------------------------------
// Kernel 1: pooled[b,c] = ( sum_{hw} x[b,c,:,:] + sum_k pe[c,k]*W[k] ) / 4096
// One block per (b,c). 256 threads * 4 float4, ld.global.cs (evict-first) so
// the 268MB x sweep doesn't pollute L2. 91% of HBM spec — at roofline.
// ---------------------------------------------------------------------------
__global__ __launch_bounds__(256) void reduce_x_kernel(
    const float* __restrict__ x, const float* __restrict__ pe,
    const float* __restrict__ conv_w, PEW pw)
{
    const int bc = blockIdx.x;
    const float4* p = reinterpret_cast<const float4*>(x) + (size_t)bc * (HW / 4);
    const int t = threadIdx.x;

    float4 a = __ldcs(p + t);
    float4 b = __ldcs(p + t + 256);
    float4 c = __ldcs(p + t + 512);
    float4 d = __ldcs(p + t + 768);

    float s = (a.x + a.y) + (a.z + a.w)
            + (b.x + b.y) + (b.z + b.w)
            + (c.x + c.y) + (c.z + c.w)
            + (d.x + d.y) + (d.z + d.w);

    #pragma unroll
    for (int off = 16; off > 0; off >>= 1)
        s += __shfl_xor_sync(0xffffffffu, s, off);

    __shared__ float ws[8];
    const int w = t >> 5, l = t & 31;
    if (l == 0) ws[w] = s;
    __syncthreads();

    if (t < 32) {
        const int cch = bc & (CCH - 1);
        const float* pc = pe + cch * 49;
        float v = (l < 8) ? ws[l] : 0.f;
        v = fmaf(pc[l], pw.w[l], v);                       // terms 0..31
        if (l < 17) v = fmaf(pc[l + 32], pw.w[l + 32], v); // terms 32..48
        #pragma unroll
        for (int off = 16; off > 0; off >>= 1)
            v += __shfl_xor_sync(0xffffffffu, v, off);
        if (l == 0) g_pooled[bc] = v * (1.0f / (float)HW);
    }

    // Tail L2 prefetch of conv_w (best-effort hint; free).
    if (bc >= RED_BLOCKS - PF_BLOCKS && t < 16) {
        const int pb = bc - (RED_BLOCKS - PF_BLOCKS);
        const float* base = conv_w + (size_t)pb * PF_FLOATS + t * 32;
        asm volatile("prefetch.global.L2 [%0];" :: "l"(base));
    }
}

// ---------------------------------------------------------------------------
// Kernel 2 (single wave): 128 blocks on 148 SMs — no serial second wave.
// Block = 8 outputs (one per warp) x 16 batches. Grid = 64 o-tiles x 2 b-groups.
// Each lane caches its conv_w row segment (4 x LDG.128) and reuses it for all
// 16 batches; pooled rows staged once in 32KB smem.
// ---------------------------------------------------------------------------
__global__ __launch_bounds__(256) void gemm_kernel(
    const float* __restrict__ conv_w,
    const float* __restrict__ conv_b,
    const float* __restrict__ gamma,
    const float* __restrict__ beta,
    const float* __restrict__ rmean,
    const float* __restrict__ rvar,
    float* __restrict__ out)
{
    const int b0 = (blockIdx.x & 1) * 16;       // batch group: 16 batches
    const int o0 = (blockIdx.x >> 1) * 8;       // output tile: 8 outputs
    const int t  = threadIdx.x;
    const int w  = t >> 5, l = t & 31;
    const int o  = o0 + w;

    // Weight row segment: 4 x float4 per lane (16 floats), coalesced 128B.
    const float4* wr4 = reinterpret_cast<const float4*>(conv_w + (size_t)o * CCH);
    float4 wv[4];
    #pragma unroll
    for (int i = 0; i < 4; i++)
        wv[i] = wr4[l + 32 * i];

    // Stage pooled rows for the 16 batches: 32KB smem.
    __shared__ float sp[16 * CCH];
    {
        const float4* src = reinterpret_cast<const float4*>(g_pooled + b0 * CCH);
        float4* dst = reinterpret_cast<float4*>(sp);
        #pragma unroll
        for (int i = 0; i < 8; i++)
            dst[t + 256 * i] = src[t + 256 * i];
    }
    __syncthreads();

    float acc[16];
    #pragma unroll
    for (int b = 0; b < 16; b++) {
        const float4* sp4 = reinterpret_cast<const float4*>(sp + b * CCH);
        float a = 0.f;
        #pragma unroll
        for (int i = 0; i < 4; i++) {
            float4 s4 = sp4[l + 32 * i];
            a = fmaf(wv[i].x, s4.x, a);
            a = fmaf(wv[i].y, s4.y, a);
            a = fmaf(wv[i].z, s4.z, a);
            a = fmaf(wv[i].w, s4.w, a);
        }
        acc[b] = a;
    }

    #pragma unroll
    for (int off = 16; off > 0; off >>= 1) {
        #pragma unroll
        for (int b = 0; b < 16; b++)
            acc[b] += __shfl_xor_sync(0xffffffffu, acc[b], off);
    }

    if (l == 0) {
        const float bias = conv_b[o];
        const float g = gamma[o], bt = beta[o], mu = rmean[o];
        const float inv = rsqrtf(rvar[o] + BN_EPS);
        #pragma unroll
        for (int b = 0; b < 16; b++) {
            float y = g * (acc[b] + bias - mu) * inv + bt;
            out[(b0 + b) * CCH + o] = fmaxf(y, 0.f);
        }
    }
}

extern "C" void kernel_launch(void* const* d_in, const int* in_sizes, int n_in,
                              void* d_out, int out_size) {
    const float* x      = (const float*)d_in[0];
    const float* pe     = (const float*)d_in[1];
    const float* conv_w = (const float*)d_in[2];
    const float* conv_b = (const float*)d_in[3];
    const float* gamma  = (const float*)d_in[4];
    const float* beta   = (const float*)d_in[5];
    const float* rmean  = (const float*)d_in[6];
    const float* rvar   = (const float*)d_in[7];
    float* out = (float*)d_out;

    // Host-side: bilinear 7->64 (half-pixel centers) column sums A[7],
    // then outer-product weights W[i*7+j] = A[i]*A[j].
    float A[7] = {0, 0, 0, 0, 0, 0, 0};
    for (int o = 0; o < 64; o++) {
        float s = (o + 0.5f) * (7.0f / 64.0f) - 0.5f;
        if (s <= 0.f)       A[0] += 1.f;
        else if (s >= 6.f)  A[6] += 1.f;
        else {
            int i0 = (int)floorf(s);
            float f = s - (float)i0;
            A[i0]     += 1.f - f;
            A[i0 + 1] += f;
        }
    }
    PEW pw;
    for (int i = 0; i < 7; i++)
        for (int j = 0; j < 7; j++)
            pw.w[i * 7 + j] = A[i] * A[j];

    reduce_x_kernel<<<RED_BLOCKS, 256>>>(x, pe, conv_w, pw);
    gemm_kernel<<<64 * 2, 256>>>(conv_w, conv_b, gamma, beta, rmean, rvar, out);
}

// round 17
// speedup vs baseline: 1.0538x; 1.0538x over previous
#include <cuda_runtime.h>
#include <math.h>

#define CCH 512
#define BB  32
#define HW  4096
#define BN_EPS 1e-5f

#define RED_BLOCKS (BB * CCH)

// Per-(b,c) pooled values (already includes pos-embed term and /4096).
__device__ float g_pooled[BB * CCH];

// 49 bilinear pooling weights A[i]*A[j], computed host-side, passed by value.
struct PEW { float w[49]; };

// ---------------------------------------------------------------------------
// Kernel 1: pooled[b,c] = ( sum_{hw} x[b,c,:,:] + sum_k pe[c,k]*W[k] ) / 4096
// One block per (b,c). 256 threads * 4 float4, ld.global.cs (evict-first) so
// the 268MB x sweep doesn't pollute L2 (91% of HBM spec — at roofline).
// Every 16th block additionally pulls 1KB of conv_w into L2 with real __ldcg
// loads (non-droppable, unlike prefetch hints) so the gemm kernel starts with
// an L2-warm weight matrix instead of cold-DRAM misses. The loaded value is
// kept alive by folding v*zero (zero is an opaque 0.0f kernel argument) into
// the pooled sum — numerically exact, not removable by the compiler.
// ---------------------------------------------------------------------------
__global__ __launch_bounds__(256) void reduce_x_kernel(
    const float* __restrict__ x, const float* __restrict__ pe,
    const float* __restrict__ conv_w, PEW pw, float zero)
{
    const int bc = blockIdx.x;
    const float4* p = reinterpret_cast<const float4*>(x) + (size_t)bc * (HW / 4);
    const int t = threadIdx.x;

    float4 a = __ldcs(p + t);
    float4 b = __ldcs(p + t + 256);
    float4 c = __ldcs(p + t + 512);
    float4 d = __ldcs(p + t + 768);

    float s = (a.x + a.y) + (a.z + a.w)
            + (b.x + b.y) + (b.z + b.w)
            + (c.x + c.y) + (c.z + c.w)
            + (d.x + d.y) + (d.z + d.w);

    // L2 warming of conv_w: 1024 blocks x 1KB (32 lanes of warp 7 load with
    // 32B stride covering 8 cache lines). Real loads — cannot be dropped.
    // Contribution v*zero == 0.0f exactly (zero is 0.0f at runtime).
    if ((bc & 15) == 0 && t >= 224) {
        const int pb = bc >> 4;                 // 0..1023
        const int lt = t - 224;                 // 0..31
        float v = __ldcg(conv_w + (size_t)pb * 256 + lt * 8);
        s = fmaf(v, zero, s);
    }

    #pragma unroll
    for (int off = 16; off > 0; off >>= 1)
        s += __shfl_xor_sync(0xffffffffu, s, off);

    __shared__ float ws[8];
    const int w = t >> 5, l = t & 31;
    if (l == 0) ws[w] = s;
    __syncthreads();

    if (t < 32) {
        const int cch = bc & (CCH - 1);
        const float* pc = pe + cch * 49;
        float v = (l < 8) ? ws[l] : 0.f;
        v = fmaf(pc[l], pw.w[l], v);                       // terms 0..31
        if (l < 17) v = fmaf(pc[l + 32], pw.w[l + 32], v); // terms 32..48
        #pragma unroll
        for (int off = 16; off > 0; off >>= 1)
            v += __shfl_xor_sync(0xffffffffu, v, off);
        if (l == 0) g_pooled[bc] = v * (1.0f / (float)HW);
    }
}

// ---------------------------------------------------------------------------
// Kernel 2: batch-amortized dense layer on (now L2-warm) weights.
// Block = 8 outputs (one per warp) x 8 batches. Grid = 64 o-tiles x 4 b-groups.
// Each lane caches its conv_w row segment (4 x LDG.128), reused for 8 batches.
// ---------------------------------------------------------------------------
__global__ __launch_bounds__(256) void gemm_kernel(
    const float* __restrict__ conv_w,
    const float* __restrict__ conv_b,
    const float* __restrict__ gamma,
    const float* __restrict__ beta,
    const float* __restrict__ rmean,
    const float* __restrict__ rvar,
    float* __restrict__ out)
{
    const int b0 = (blockIdx.x & 3) * 8;        // batch group: 8 batches
    const int o0 = (blockIdx.x >> 2) * 8;       // output tile: 8 outputs
    const int t  = threadIdx.x;
    const int w  = t >> 5, l = t & 31;
    const int o  = o0 + w;

    // Weight row segment: 4 x float4 per lane (16 floats), coalesced 128B.
    const float4* wr4 = reinterpret_cast<const float4*>(conv_w + (size_t)o * CCH);
    float4 wv[4];
    #pragma unroll
    for (int i = 0; i < 4; i++)
        wv[i] = wr4[l + 32 * i];

    // Stage pooled rows for the 8 batches: 16KB smem (L2-resident source).
    __shared__ float sp[8 * CCH];
    {
        const float4* src = reinterpret_cast<const float4*>(g_pooled + b0 * CCH);
        float4* dst = reinterpret_cast<float4*>(sp);
        #pragma unroll
        for (int i = 0; i < 4; i++)
            dst[t + 256 * i] = src[t + 256 * i];
    }
    __syncthreads();

    float acc[8];
    #pragma unroll
    for (int b = 0; b < 8; b++) {
        const float4* sp4 = reinterpret_cast<const float4*>(sp + b * CCH);
        float a = 0.f;
        #pragma unroll
        for (int i = 0; i < 4; i++) {
            float4 s4 = sp4[l + 32 * i];
            a = fmaf(wv[i].x, s4.x, a);
            a = fmaf(wv[i].y, s4.y, a);
            a = fmaf(wv[i].z, s4.z, a);
            a = fmaf(wv[i].w, s4.w, a);
        }
        acc[b] = a;
    }

    #pragma unroll
    for (int off = 16; off > 0; off >>= 1) {
        #pragma unroll
        for (int b = 0; b < 8; b++)
            acc[b] += __shfl_xor_sync(0xffffffffu, acc[b], off);
    }

    if (l == 0) {
        const float bias = conv_b[o];
        const float g = gamma[o], bt = beta[o], mu = rmean[o];
        const float inv = rsqrtf(rvar[o] + BN_EPS);
        #pragma unroll
        for (int b = 0; b < 8; b++) {
            float y = g * (acc[b] + bias - mu) * inv + bt;
            out[(b0 + b) * CCH + o] = fmaxf(y, 0.f);
        }
    }
}

extern "C" void kernel_launch(void* const* d_in, const int* in_sizes, int n_in,
                              void* d_out, int out_size) {
    const float* x      = (const float*)d_in[0];
    const float* pe     = (const float*)d_in[1];
    const float* conv_w = (const float*)d_in[2];
    const float* conv_b = (const float*)d_in[3];
    const float* gamma  = (const float*)d_in[4];
    const float* beta   = (const float*)d_in[5];
    const float* rmean  = (const float*)d_in[6];
    const float* rvar   = (const float*)d_in[7];
    float* out = (float*)d_out;

    // Host-side: bilinear 7->64 (half-pixel centers) column sums A[7],
    // then outer-product weights W[i*7+j] = A[i]*A[j].
    float A[7] = {0, 0, 0, 0, 0, 0, 0};
    for (int o = 0; o < 64; o++) {
        float s = (o + 0.5f) * (7.0f / 64.0f) - 0.5f;
        if (s <= 0.f)       A[0] += 1.f;
        else if (s >= 6.f)  A[6] += 1.f;
        else {
            int i0 = (int)floorf(s);
            float f = s - (float)i0;
            A[i0]     += 1.f - f;
            A[i0 + 1] += f;
        }
    }
    PEW pw;
    for (int i = 0; i < 7; i++)
        for (int j = 0; j < 7; j++)
            pw.w[i * 7 + j] = A[i] * A[j];

    reduce_x_kernel<<<RED_BLOCKS, 256>>>(x, pe, conv_w, pw, 0.0f);
    gemm_kernel<<<64 * 4, 256>>>(conv_w, conv_b, gamma, beta, rmean, rvar, out);
}